// round 11
// baseline (speedup 1.0000x reference)
#include <cuda_runtime.h>
#include <cstdint>

#define B_  64
#define T_  2048
#define IN_ 64
#define H_  256
#define BT  (B_*T_)

#define ALPHA  0.2f
#define OMA    0.8f   // 1 - alpha

// Scratch for P = I @ W_in^T + b, padded by 2 steps for branchless prefetch.
__device__ float g_P[((size_t)BT + 2) * H_];

typedef unsigned long long u64;

__device__ __forceinline__ void ffma2(u64 &acc, u64 a, u64 b) {
    asm("fma.rn.f32x2 %0, %1, %2, %0;" : "+l"(acc) : "l"(a), "l"(b));
}
__device__ __forceinline__ u64 fadd2(u64 a, u64 b) {
    u64 r;
    asm("add.rn.f32x2 %0, %1, %2;" : "=l"(r) : "l"(a), "l"(b));
    return r;
}
__device__ __forceinline__ float lo32(u64 v) { return __uint_as_float((unsigned)v); }
__device__ __forceinline__ float hi32(u64 v) { return __uint_as_float((unsigned)(v >> 32)); }

__device__ __forceinline__ float tanh_fast(float x) {
    x = fminf(fmaxf(x, -20.f), 20.f);
    float e = __expf(2.f * x);
    return __fdividef(e - 1.f, e + 1.f);
}

__device__ __forceinline__ uint32_t smem_u32(const void* p) {
    uint32_t a;
    asm("{ .reg .u64 t; cvta.to.shared.u64 t, %1; cvt.u32.u64 %0, t; }"
        : "=r"(a) : "l"(p));
    return a;
}

// ---------------------------------------------------------------------------
// Kernel 1: P[bt][h] = I[bt] @ W_in[h] + b[h]   (unchanged from R9 — correct)
// ---------------------------------------------------------------------------
__global__ void __launch_bounds__(256) pre_kernel(const float* __restrict__ I,
                                                  const float* __restrict__ Win,
                                                  const float* __restrict__ bvec) {
    __shared__ ulonglong2 sI[16 * 16];  // 16 rows x 64 floats
    const int row0 = blockIdx.x * 16;
    const int tid  = threadIdx.x;

    {
        const ulonglong2* I16 = (const ulonglong2*)(I + (size_t)row0 * IN_);
        sI[tid] = I16[tid];
    }
    __syncthreads();

    const int h = tid;
    u64 w2[32];
    const u64* W2 = (const u64*)(Win + h * IN_);
#pragma unroll
    for (int j = 0; j < 32; j++) w2[j] = W2[j];
    const float bb = bvec[h];

#pragma unroll 4
    for (int r = 0; r < 16; r++) {
        u64 aA = 0ull, aB = 0ull;
        const ulonglong2* ir = &sI[r * 16];
#pragma unroll
        for (int j4 = 0; j4 < 16; j4++) {
            ulonglong2 iv = ir[j4];
            ffma2(aA, w2[2 * j4 + 0], iv.x);
            ffma2(aB, w2[2 * j4 + 1], iv.y);
        }
        float acc = (lo32(aA) + hi32(aA)) + (lo32(aB) + hi32(aB)) + bb;
        g_P[(size_t)(row0 + r) * H_ + h] = acc;
    }
}

// ---------------------------------------------------------------------------
// Kernel 2: recurrence on 2-CTA clusters. 128 CTAs; cluster = one batch row.
// CTA rank owns h in [rank*128, rank*128+128). 256 threads: thread = (h_local,
// khalf); each holds 128 k-cols of W_rec row h in 64 u64 regs (FULL W in RF,
// no SMEM-W). r exchanged per step: even lane stores local half, odd lane
// pushes to peer CTA via st.shared::cluster; mbarrier handshake.
// rbuf layout per buffer: [0..127] khalf0, 4-float pad (bank shift), [132..259]
// khalf1, tail pad to 272 for the 2-deep prefetch over-read.
// ---------------------------------------------------------------------------
#define RSTRIDE 272

__global__ void __launch_bounds__(256, 1) __cluster_dims__(2, 1, 1)
rec_kernel(const float* __restrict__ x0,
           const float* __restrict__ Wrec,
           float* __restrict__ out_u) {
    __shared__ __align__(16) float rbuf[2 * RSTRIDE];
    __shared__ __align__(8)  u64   mbar[2];

    const int tid     = threadIdx.x;
    const int h_local = tid >> 1;
    const int khalf   = tid & 1;
    const int b       = blockIdx.x >> 1;
    const uint32_t rank = blockIdx.x & 1;
    const uint32_t peer = rank ^ 1u;
    const int h = (int)rank * 128 + h_local;

    // Full W row-half in registers: 128 floats = 64 u64 pairs.
    u64 wr2[64];
    const u64* Wr = (const u64*)(Wrec + (size_t)h * H_ + khalf * 128);
#pragma unroll
    for (int j = 0; j < 64; j++) wr2[j] = Wr[j];

    if (tid == 0) {
        asm volatile("mbarrier.init.shared.b64 [%0], 1;" ::
                     "r"(smem_u32(&mbar[0])) : "memory");
        asm volatile("mbarrier.init.shared.b64 [%0], 1;" ::
                     "r"(smem_u32(&mbar[1])) : "memory");
    }
    __syncthreads();
    // cluster-wide: peers' mbarrier init + SMEM ready before any remote ops
    asm volatile("barrier.cluster.arrive.aligned;" ::: "memory");
    asm volatile("barrier.cluster.wait.aligned;"   ::: "memory");

    // Remote addresses (peer CTA's rbuf / mbar) via mapa.
    uint32_t rbuf_l = smem_u32(rbuf);
    uint32_t mbar_l = smem_u32(mbar);
    uint32_t rbuf_r, mbar_r;
    asm("mapa.shared::cluster.u32 %0, %1, %2;" : "=r"(rbuf_r) : "r"(rbuf_l), "r"(peer));
    asm("mapa.shared::cluster.u32 %0, %1, %2;" : "=r"(mbar_r) : "r"(mbar_l), "r"(peer));

    float u = x0[b * H_ + h];
    const float* Pb = g_P + (size_t)b * T_ * H_ + h;
    float* ub = out_u + (size_t)b * T_ * H_ + h;
    float pv0 = __ldg(Pb);
    float pv1 = __ldg(Pb + H_);

    // r slot index within a buffer (pad-shifted second half)
    const int slot = (h < 128) ? h : (h + 4);

    for (int t = 0; t < T_; t++) {
        const int p = t & 1;
        const float r = tanh_fast(u);

        if (khalf == 0) {
            rbuf[p * RSTRIDE + slot] = r;                       // local half
        } else {
            asm volatile("st.shared::cluster.f32 [%0], %1;" ::
                         "r"(rbuf_r + (p * RSTRIDE + slot) * 4), "f"(r)
                         : "memory");                           // push to peer
        }
        __syncthreads();
        if (tid == 0) {
            asm volatile("fence.acq_rel.cluster;" ::: "memory");
            asm volatile("mbarrier.arrive.release.cluster.shared::cluster.b64 _, [%0];"
                         :: "r"(mbar_r + p * 8) : "memory");
        }
        {   // wait for peer's half (acquire, cluster scope), parity (t>>1)&1
            const uint32_t bar = mbar_l + p * 8;
            const uint32_t par = (t >> 1) & 1;
            uint32_t done;
            asm volatile(
                "{\n\t.reg .pred q;\n\t"
                "mbarrier.try_wait.parity.acquire.cluster.shared::cta.b64 q, [%1], %2;\n\t"
                "selp.b32 %0, 1, 0, q;\n\t}"
                : "=r"(done) : "r"(bar), "r"(par) : "memory");
            if (!done) {
                asm volatile(
                    "{\n\t.reg .pred q;\n\t"
                    "WL_%=:\n\t"
                    "mbarrier.try_wait.parity.acquire.cluster.shared::cta.b64 q, [%0], %1, 0x989680;\n\t"
                    "@q bra.uni WD_%=;\n\t"
                    "bra.uni WL_%=;\n\t"
                    "WD_%=:\n\t}"
                    :: "r"(bar), "r"(par) : "memory");
            }
        }

        // Matvec over this thread's 128 k: 32 LDS.128 chunks, 2 acc chains,
        // 2-deep prefetch. khalf1 reads the pad-shifted upper region.
        const ulonglong2* r16 =
            (const ulonglong2*)(rbuf + p * RSTRIDE + (khalf ? 132 : 0));
        u64 aA = 0ull, aB = 0ull;
        ulonglong2 p0 = r16[0];
        ulonglong2 p1 = r16[1];
#pragma unroll
        for (int c = 0; c < 32; c++) {
            ulonglong2 cur = p0;
            p0 = p1;
            p1 = r16[c + 2];                 // over-read lands in pads: safe
            ffma2(aA, wr2[2 * c],     cur.x);
            ffma2(aB, wr2[2 * c + 1], cur.y);
        }
        u64 s = fadd2(aA, aB);
        float part = lo32(s) + hi32(s);
        part += __shfl_xor_sync(0xffffffffu, part, 1);   // sum the two k-halves

        float drive = part + pv0;
        u = fmaf(OMA, u, ALPHA * drive);
        if (khalf == 0) ub[(size_t)t * H_] = u;          // 16 lanes/warp, contiguous h

        pv0 = pv1;
        pv1 = __ldg(Pb + (size_t)(t + 2) * H_);          // padded: branchless
    }

    // no CTA may exit while peer remote-stores could be in flight
    asm volatile("barrier.cluster.arrive.aligned;" ::: "memory");
    asm volatile("barrier.cluster.wait.aligned;"   ::: "memory");
}

// ---------------------------------------------------------------------------
// Kernel 3: y[bt][j] = u[bt] @ Wout[j] + bout[j].  Warp per row.
// ---------------------------------------------------------------------------
__global__ void __launch_bounds__(256) y_kernel(const float* __restrict__ u,
                                                const float* __restrict__ Wout,
                                                const float* __restrict__ bout,
                                                float* __restrict__ y) {
    const int warp = threadIdx.x >> 5;
    const int lane = threadIdx.x & 31;
    const size_t row = (size_t)blockIdx.x * 8 + warp;

    const float4* u4  = (const float4*)(u + row * H_);
    const float4* w04 = (const float4*)(Wout);
    const float4* w14 = (const float4*)(Wout + H_);

    float s0 = 0.f, s1 = 0.f;
#pragma unroll
    for (int j = 0; j < 2; j++) {
        int idx = j * 32 + lane;
        float4 a  = u4[idx];
        float4 w0 = w04[idx];
        float4 w1 = w14[idx];
        s0 += a.x * w0.x + a.y * w0.y + a.z * w0.z + a.w * w0.w;
        s1 += a.x * w1.x + a.y * w1.y + a.z * w1.z + a.w * w1.w;
    }
#pragma unroll
    for (int off = 16; off; off >>= 1) {
        s0 += __shfl_xor_sync(0xffffffffu, s0, off);
        s1 += __shfl_xor_sync(0xffffffffu, s1, off);
    }
    if (lane == 0) {
        y[row * 2 + 0] = s0 + bout[0];
        y[row * 2 + 1] = s1 + bout[1];
    }
}

// ---------------------------------------------------------------------------
// Launch. Inputs: x0, I, W_in, W_rec, b, Wout, bout.
// Output: [u (B*T*H) | y (B*T*2)] concatenated.
// ---------------------------------------------------------------------------
extern "C" void kernel_launch(void* const* d_in, const int* in_sizes, int n_in,
                              void* d_out, int out_size) {
    const float* x0   = (const float*)d_in[0];
    const float* I    = (const float*)d_in[1];
    const float* Win  = (const float*)d_in[2];
    const float* Wrec = (const float*)d_in[3];
    const float* bv   = (const float*)d_in[4];
    const float* Wout = (const float*)d_in[5];
    const float* bout = (const float*)d_in[6];

    float* out_u = (float*)d_out;
    float* out_y = out_u + (size_t)BT * H_;

    pre_kernel<<<BT / 16, 256>>>(I, Win, bv);
    rec_kernel<<<2 * B_, 256>>>(x0, Wrec, out_u);   // 64 clusters of 2 CTAs
    y_kernel<<<BT / 8, 256>>>(out_u, Wout, bout, out_y);
}

// round 12
// speedup vs baseline: 1.0976x; 1.0976x over previous
#include <cuda_runtime.h>
#include <cstdint>

#define B_  64
#define T_  2048
#define IN_ 64
#define H_  256
#define BT  (B_*T_)

#define ALPHA  0.2f
#define OMA    0.8f   // 1 - alpha

// Scratch for P = I @ W_in^T + b, padded by 2 steps for branchless prefetch.
__device__ float g_P[((size_t)BT + 2) * H_];

typedef unsigned long long u64;

__device__ __forceinline__ void ffma2(u64 &acc, u64 a, u64 b) {
    asm("fma.rn.f32x2 %0, %1, %2, %0;" : "+l"(acc) : "l"(a), "l"(b));
}
__device__ __forceinline__ u64 fadd2(u64 a, u64 b) {
    u64 r;
    asm("add.rn.f32x2 %0, %1, %2;" : "=l"(r) : "l"(a), "l"(b));
    return r;
}
__device__ __forceinline__ float lo32(u64 v) { return __uint_as_float((unsigned)v); }
__device__ __forceinline__ float hi32(u64 v) { return __uint_as_float((unsigned)(v >> 32)); }

// tanh via MUFU EX2 + MUFU RCP. rel err ~1e-6, far inside the 1e-3 budget.
__device__ __forceinline__ float tanh_fast(float x) {
    x = fminf(fmaxf(x, -20.f), 20.f);
    float e = __expf(2.f * x);
    return __fdividef(e - 1.f, e + 1.f);
}

// ---------------------------------------------------------------------------
// Kernel 1: P[bt][h] = I[bt] @ W_in[h] + b[h]
// khalf-split for occupancy: thread = (h_local, khalf); W regs 32 floats;
// grid.y = 2 picks the h-half. ~60 regs -> 4 CTAs/SM (32 warps).
// I rows staged bank-padded: [0..31][pad4][32..63] per row (stride 68) so the
// paired lane addresses (khalf 0/1) hit disjoint banks -> 1 wf per LDS.128.
// ---------------------------------------------------------------------------
__global__ void __launch_bounds__(256) pre_kernel(const float* __restrict__ I,
                                                  const float* __restrict__ Win,
                                                  const float* __restrict__ bvec) {
    __shared__ float sI[16 * 68];       // 16 rows, padded stride 68 floats
    const int tid  = threadIdx.x;
    const int row0 = blockIdx.x * 16;
    const int hhalf = blockIdx.y;

    {   // stage 16 rows x 16 chunks, one 16B chunk per thread, coalesced
        const int r  = tid >> 4;
        const int jc = tid & 15;
        const ulonglong2* I16 = (const ulonglong2*)(I + (size_t)row0 * IN_);
        ulonglong2 v = I16[tid];
        const int off = r * 68 + jc * 4 + (jc >= 8 ? 4 : 0);
        *(ulonglong2*)(sI + off) = v;
    }
    __syncthreads();

    const int h_local = tid >> 1;
    const int khalf   = tid & 1;
    const int h = hhalf * 128 + h_local;

    u64 w2[16];                          // 32 floats of W_in row h
    const u64* W2 = (const u64*)(Win + (size_t)h * IN_ + khalf * 32);
#pragma unroll
    for (int j = 0; j < 16; j++) w2[j] = W2[j];
    const float bb = bvec[h];

#pragma unroll 4
    for (int r = 0; r < 16; r++) {
        u64 aA = 0ull, aB = 0ull;
        const ulonglong2* ir = (const ulonglong2*)(sI + r * 68 + khalf * 36);
#pragma unroll
        for (int c = 0; c < 8; c++) {
            ulonglong2 iv = ir[c];       // 2 addrs/warp, disjoint banks: 1 wf
            ffma2(aA, w2[2 * c + 0], iv.x);
            ffma2(aB, w2[2 * c + 1], iv.y);
        }
        float acc = (lo32(aA) + hi32(aA)) + (lo32(aB) + hi32(aB));
        acc += __shfl_xor_sync(0xffffffffu, acc, 1);     // join k-halves
        if (khalf == 0)
            g_P[(size_t)(row0 + r) * H_ + h] = acc + bb;
    }
}

// ---------------------------------------------------------------------------
// Kernel 2: persistent recurrence. 64 CTAs (one per batch), 512 threads:
// thread = (h, khalf), each owns 128 k-cols of W_rec row h:
//   - 96 k in registers (48 u64 pairs, ~116 regs total, fits 128/thr @512)
//   - 32 k in SMEM [c][tid] (64 KB, conflict-free LDS.128)
// 16 warps (4/SMSP) to overlap the LDS crossbar stream with FFMA2 issue.
// r double-buffered in SMEM with a 4-float pad between k-halves so paired
// lane addresses hit disjoint banks. ONE __syncthreads per step; k-halves
// joined with one shfl_xor(1).
// ---------------------------------------------------------------------------
#define NRC 24    // register float4-chunks per thread (96 k-cols, 96 regs)
#define NSC 8     // SMEM float4-chunks per thread     (32 k-cols)
#define RST 272   // r buffer stride in floats (128 | pad4 | 128 | tail pad)

__global__ void __launch_bounds__(512, 1) rec_kernel(const float* __restrict__ x0,
                                                     const float* __restrict__ Wrec,
                                                     float* __restrict__ out_u) {
    extern __shared__ float smem[];
    ulonglong2* wsm = (ulonglong2*)smem;                 // [NSC][512] = 64 KB
    float* rbuf = smem + NSC * 512 * 4;                  // 2 x RST floats

    const int tid   = threadIdx.x;
    const int h     = tid >> 1;
    const int khalf = tid & 1;
    const int b     = blockIdx.x;

    // SMEM part of W: last NSC chunks of this thread's 128-col range.
    const float4* Wrow4 = (const float4*)(Wrec + (size_t)h * H_ + khalf * 128);
#pragma unroll
    for (int c = 0; c < NSC; c++) {
        float4 v = Wrow4[NRC + c];
        wsm[c * 512 + tid] = *(ulonglong2*)&v;
    }

    // Register part of W: first 96 k-cols = 48 u64 pairs.
    u64 wr2[2 * NRC];
    const u64* Wr = (const u64*)(Wrec + (size_t)h * H_ + khalf * 128);
#pragma unroll
    for (int j = 0; j < 2 * NRC; j++) wr2[j] = Wr[j];

    float u = x0[b * H_ + h];
    const float* Pb = g_P + (size_t)b * T_ * H_ + h;
    float* ub = out_u + (size_t)b * T_ * H_ + h;
    float pv0 = __ldg(Pb);
    float pv1 = __ldg(Pb + H_);

    const int slot = (h < 128) ? h : (h + 4);   // pad-shifted upper half
    __syncthreads();

    for (int t = 0; t < T_; t++) {
        const int p = t & 1;
        const float r = tanh_fast(u);

        if (khalf == 0) rbuf[p * RST + slot] = r;   // even threads cover all h
        __syncthreads();

        // This thread's 128 r values, base shifted by khalf (bank-disjoint).
        const ulonglong2* r16 = (const ulonglong2*)(rbuf + p * RST + khalf * 132);
        u64 aA = 0ull, aB = 0ull;
#pragma unroll
        for (int c = 0; c < NRC; c++) {
            ulonglong2 rr = r16[c];                  // 2 addrs/warp, 1 wf
            ffma2(aA, wr2[2 * c + 0], rr.x);
            ffma2(aB, wr2[2 * c + 1], rr.y);
        }
#pragma unroll
        for (int c = 0; c < NSC; c++) {
            ulonglong2 rr = r16[NRC + c];
            ulonglong2 wv = wsm[c * 512 + tid];      // coalesced, 4 wf
            ffma2(aA, wv.x, rr.x);
            ffma2(aB, wv.y, rr.y);
        }

        u64 s = fadd2(aA, aB);
        float part = lo32(s) + hi32(s);
        part += __shfl_xor_sync(0xffffffffu, part, 1);   // join k-halves

        u = fmaf(OMA, u, ALPHA * (part + pv0));
        if (khalf == 0) ub[(size_t)t * H_] = u;

        pv0 = pv1;
        pv1 = __ldg(Pb + (size_t)(t + 2) * H_);      // padded: branchless
    }
}

// ---------------------------------------------------------------------------
// Kernel 3: y[bt][j] = u[bt] @ Wout[j] + bout[j].  Warp per row.
// ---------------------------------------------------------------------------
__global__ void __launch_bounds__(256) y_kernel(const float* __restrict__ u,
                                                const float* __restrict__ Wout,
                                                const float* __restrict__ bout,
                                                float* __restrict__ y) {
    const int warp = threadIdx.x >> 5;
    const int lane = threadIdx.x & 31;
    const size_t row = (size_t)blockIdx.x * 8 + warp;

    const float4* u4  = (const float4*)(u + row * H_);
    const float4* w04 = (const float4*)(Wout);
    const float4* w14 = (const float4*)(Wout + H_);

    float s0 = 0.f, s1 = 0.f;
#pragma unroll
    for (int j = 0; j < 2; j++) {
        int idx = j * 32 + lane;
        float4 a  = u4[idx];
        float4 w0 = w04[idx];
        float4 w1 = w14[idx];
        s0 += a.x * w0.x + a.y * w0.y + a.z * w0.z + a.w * w0.w;
        s1 += a.x * w1.x + a.y * w1.y + a.z * w1.z + a.w * w1.w;
    }
#pragma unroll
    for (int off = 16; off; off >>= 1) {
        s0 += __shfl_xor_sync(0xffffffffu, s0, off);
        s1 += __shfl_xor_sync(0xffffffffu, s1, off);
    }
    if (lane == 0) {
        y[row * 2 + 0] = s0 + bout[0];
        y[row * 2 + 1] = s1 + bout[1];
    }
}

// ---------------------------------------------------------------------------
// Launch. Inputs: x0, I, W_in, W_rec, b, Wout, bout.
// Output: [u (B*T*H) | y (B*T*2)] concatenated.
// ---------------------------------------------------------------------------
extern "C" void kernel_launch(void* const* d_in, const int* in_sizes, int n_in,
                              void* d_out, int out_size) {
    const float* x0   = (const float*)d_in[0];
    const float* I    = (const float*)d_in[1];
    const float* Win  = (const float*)d_in[2];
    const float* Wrec = (const float*)d_in[3];
    const float* bv   = (const float*)d_in[4];
    const float* Wout = (const float*)d_in[5];
    const float* bout = (const float*)d_in[6];

    float* out_u = (float*)d_out;
    float* out_y = out_u + (size_t)BT * H_;

    const int smem_bytes = NSC * 512 * 16 + 2 * RST * 4;   // 65536 + 2176
    cudaFuncSetAttribute(rec_kernel, cudaFuncAttributeMaxDynamicSharedMemorySize,
                         smem_bytes);

    pre_kernel<<<dim3(BT / 16, 2), 256>>>(I, Win, bv);
    rec_kernel<<<B_, 512, smem_bytes>>>(x0, Wrec, out_u);
    y_kernel<<<BT / 8, 256>>>(out_u, Wout, bout, out_y);
}